// round 2
// baseline (speedup 1.0000x reference)
#include <cuda_runtime.h>
#include <math.h>

#define N_TOK   8192
#define DMODEL  256
#define NEXP    16
#define NVIEW   3
#define TOPK    4
#define HDIM    1024
#define ASSIGN_TOTAL (NVIEW * N_TOK * TOPK)   /* 98304 */
#define CAP     ASSIGN_TOTAL

#define BM      64      /* rows per MLP CTA           */
#define CH      64      /* hidden chunk               */
#define TPB     256

/* ---------------- device scratch (static, allocation-free) ---------------- */
__device__ float g_comb[NVIEW * NEXP * DMODEL];   /* 2*k_e + rw[v,e]    */
__device__ float g_kn2[NEXP];                     /* |k_e|^2            */
__device__ int   g_cnt[NEXP];                     /* rows per expert    */
__device__ int2  g_bucket[NEXP * CAP];            /* {view*8192+tok, gate bits}, 12.6 MB */

/* ---------------- kernel 0: zero output + counters ---------------- */
__global__ void zero_kernel(float* __restrict__ out) {
    int i = blockIdx.x * blockDim.x + threadIdx.x;
    if (i < N_TOK * DMODEL) out[i] = 0.0f;
    if (i < NEXP) g_cnt[i] = 0;
}

/* ---------------- kernel 1: precompute combined router weights ---------------- */
__global__ void prep_kernel(const float* __restrict__ rw, const float* __restrict__ ek) {
    int t = threadIdx.x;              /* 256 threads, 8 warps */
    int lane = t & 31, w = t >> 5;
    for (int e = w; e < NEXP; e += 8) {
        float s = 0.f;
        #pragma unroll
        for (int j = 0; j < DMODEL; j += 32) {
            float x = ek[e * DMODEL + lane + j];
            s += x * x;
        }
        #pragma unroll
        for (int o = 16; o; o >>= 1) s += __shfl_xor_sync(0xffffffffu, s, o);
        if (lane == 0) g_kn2[e] = s;
    }
    for (int i = t; i < NVIEW * NEXP * DMODEL; i += TPB) {
        int e = (i >> 8) & 15;
        int d = i & 255;
        g_comb[i] = 2.0f * ek[e * DMODEL + d] + rw[i];
    }
}

/* ---------------- kernel 2: gating + routing scatter ---------------- */
/* one warp per (view, token).  logits[e] = v . (2k_e + rw) - |k_e|^2
   (per-token -|v|^2 dropped: invariant under top-k and softmax)      */
__global__ void gate_kernel(const float* __restrict__ v0,
                            const float* __restrict__ v1,
                            const float* __restrict__ v2) {
    int wg   = (blockIdx.x * blockDim.x + threadIdx.x) >> 5;
    int lane = threadIdx.x & 31;
    if (wg >= NVIEW * N_TOK) return;
    int view = wg >> 13;              /* / 8192 */
    int tok  = wg & (N_TOK - 1);
    const float* vp = (view == 0 ? v0 : (view == 1 ? v1 : v2)) + tok * DMODEL;

    float xr[8];
    #pragma unroll
    for (int j = 0; j < 8; j++) xr[j] = vp[lane + 32 * j];

    float lg[NEXP];
    const float* cb = g_comb + view * NEXP * DMODEL;
    #pragma unroll
    for (int e = 0; e < NEXP; e++) {
        float p = 0.f;
        #pragma unroll
        for (int j = 0; j < 8; j++) p += xr[j] * cb[e * DMODEL + lane + 32 * j];
        #pragma unroll
        for (int o = 16; o; o >>= 1) p += __shfl_xor_sync(0xffffffffu, p, o);
        lg[e] = p - g_kn2[e];
    }

    if (lane == 0) {
        float tv[TOPK]; int ti[TOPK];
        unsigned used = 0;
        #pragma unroll
        for (int k = 0; k < TOPK; k++) {
            float best = -3.0e38f; int bi = 0;
            #pragma unroll
            for (int e = 0; e < NEXP; e++)
                if (!((used >> e) & 1u) && lg[e] > best) { best = lg[e]; bi = e; }
            used |= 1u << bi;
            tv[k] = best; ti[k] = bi;
        }
        float mx = tv[0];
        float ex[TOPK]; float s = 0.f;
        #pragma unroll
        for (int k = 0; k < TOPK; k++) { ex[k] = expf(tv[k] - mx); s += ex[k]; }
        float inv = 1.0f / s;
        #pragma unroll
        for (int k = 0; k < TOPK; k++) {
            int e = ti[k];
            int slot = atomicAdd(&g_cnt[e], 1);
            g_bucket[e * CAP + slot] = make_int2(wg, __float_as_int(ex[k] * inv));
        }
    }
}

/* ---------------- kernel 3: grouped fused MLP ---------------- */
/* CTA = (expert e, 64 assignment rows).  acc = gelu(X @ W1 + b1) @ W2,
   computed in 16 hidden chunks of 64; out[tok] += gate*(acc + b2).   */
__device__ __forceinline__ float gelu_exact(float x) {
    return 0.5f * x * (1.0f + erff(x * 0.70710678118654752f));
}

#define XS_LD  260          /* X row pitch (floats)   */
#define WH_LD  68           /* W1s/Hs row pitch       */
#define W2_LD  260          /* W2s row pitch          */
#define SMEM_FLOATS (BM * XS_LD + BM * WH_LD + 16 * W2_LD)   /* 25152 -> 100608 B */

__global__ __launch_bounds__(TPB)
void mlp_kernel(const float* __restrict__ v0, const float* __restrict__ v1,
                const float* __restrict__ v2,
                const float* __restrict__ W1, const float* __restrict__ b1,
                const float* __restrict__ W2, const float* __restrict__ b2,
                float* __restrict__ out) {
    int e   = blockIdx.y;
    int cnt = g_cnt[e];
    int r0  = blockIdx.x * BM;
    if (r0 >= cnt) return;

    extern __shared__ float sm[];
    float* Xs  = sm;                     /* [64][260] */
    float* WHs = sm + BM * XS_LD;        /* [64][68]  W1 chunk, then reused as H */
    float* W2s = WHs + BM * WH_LD;       /* [16][260] */

    __shared__ const float* s_ptr[BM];
    __shared__ float        s_gate[BM];
    __shared__ int          s_tok[BM];

    int t = threadIdx.x;

    if (t < BM) {
        int gr = r0 + t;
        if (gr < cnt) {
            int2 rec = g_bucket[e * CAP + gr];
            int view = rec.x >> 13;
            int tok  = rec.x & (N_TOK - 1);
            s_ptr[t]  = (view == 0 ? v0 : (view == 1 ? v1 : v2)) + tok * DMODEL;
            s_tok[t]  = tok;
            s_gate[t] = __int_as_float(rec.y);
        } else {
            s_ptr[t] = v0; s_tok[t] = 0; s_gate[t] = 0.f;
        }
    }
    __syncthreads();

    /* cooperative X load: 4 rows in flight, 64 float4 per row */
    {
        int rowg = t >> 6;       /* 0..3 */
        int c4   = t & 63;       /* 0..63 */
        #pragma unroll
        for (int it = 0; it < 16; it++) {
            int m = it * 4 + rowg;
            float4 val = ((const float4*)s_ptr[m])[c4];
            *(float4*)&Xs[m * XS_LD + c4 * 4] = val;
        }
    }

    int tx = t & 15, ty = t >> 4;
    float acc[64];
    #pragma unroll
    for (int i = 0; i < 64; i++) acc[i] = 0.f;

    const float* W1e = W1 + (size_t)e * DMODEL * HDIM;
    const float* W2e = W2 + (size_t)e * HDIM * DMODEL;
    const float* b1e = b1 + e * HDIM;

    __syncthreads();

    for (int hc = 0; hc < HDIM; hc += CH) {
        /* ---- GEMM1: H[64][64] = X @ W1[:, hc:hc+64] + b1 ---- */
        float hreg[16];
        #pragma unroll
        for (int i = 0; i < 4; i++)
            #pragma unroll
            for (int j = 0; j < 4; j++)
                hreg[i * 4 + j] = b1e[hc + tx * 4 + j];

        #pragma unroll
        for (int kt = 0; kt < 4; kt++) {
            /* stage W1 k-tile [64][64] */
            #pragma unroll
            for (int j = 0; j < 4; j++) {
                int id = t + TPB * j;
                int kk = id >> 4, c4 = id & 15;
                *(float4*)&WHs[kk * WH_LD + c4 * 4] =
                    *(const float4*)&W1e[(size_t)(kt * 64 + kk) * HDIM + hc + c4 * 4];
            }
            __syncthreads();
            #pragma unroll
            for (int kk = 0; kk < 64; kk++) {
                float a0 = Xs[(ty * 4 + 0) * XS_LD + kt * 64 + kk];
                float a1 = Xs[(ty * 4 + 1) * XS_LD + kt * 64 + kk];
                float a2 = Xs[(ty * 4 + 2) * XS_LD + kt * 64 + kk];
                float a3 = Xs[(ty * 4 + 3) * XS_LD + kt * 64 + kk];
                float4 bv = *(float4*)&WHs[kk * WH_LD + tx * 4];
                hreg[0]  += a0 * bv.x; hreg[1]  += a0 * bv.y; hreg[2]  += a0 * bv.z; hreg[3]  += a0 * bv.w;
                hreg[4]  += a1 * bv.x; hreg[5]  += a1 * bv.y; hreg[6]  += a1 * bv.z; hreg[7]  += a1 * bv.w;
                hreg[8]  += a2 * bv.x; hreg[9]  += a2 * bv.y; hreg[10] += a2 * bv.z; hreg[11] += a2 * bv.w;
                hreg[12] += a3 * bv.x; hreg[13] += a3 * bv.y; hreg[14] += a3 * bv.z; hreg[15] += a3 * bv.w;
            }
            __syncthreads();
        }

        /* gelu, then park H in the (now dead) W1 staging buffer */
        #pragma unroll
        for (int i = 0; i < 4; i++) {
            float4 hv;
            hv.x = gelu_exact(hreg[i * 4 + 0]);
            hv.y = gelu_exact(hreg[i * 4 + 1]);
            hv.z = gelu_exact(hreg[i * 4 + 2]);
            hv.w = gelu_exact(hreg[i * 4 + 3]);
            *(float4*)&WHs[(ty * 4 + i) * WH_LD + tx * 4] = hv;
        }
        __syncthreads();

        /* ---- GEMM2: acc[64][256] += H @ W2[hc:hc+64, :] ---- */
        #pragma unroll
        for (int k2t = 0; k2t < 4; k2t++) {
            #pragma unroll
            for (int j = 0; j < 4; j++) {
                int id = t + TPB * j;
                int kk = id >> 6, c4 = id & 63;
                *(float4*)&W2s[kk * W2_LD + c4 * 4] =
                    *(const float4*)&W2e[(size_t)(hc + k2t * 16 + kk) * DMODEL + c4 * 4];
            }
            __syncthreads();
            #pragma unroll
            for (int kk = 0; kk < 16; kk++) {
                float a[4];
                #pragma unroll
                for (int i = 0; i < 4; i++)
                    a[i] = WHs[(ty * 4 + i) * WH_LD + k2t * 16 + kk];
                #pragma unroll
                for (int q = 0; q < 4; q++) {
                    float4 bv = *(float4*)&W2s[kk * W2_LD + q * 64 + tx * 4];
                    #pragma unroll
                    for (int i = 0; i < 4; i++) {
                        acc[i * 16 + q * 4 + 0] += a[i] * bv.x;
                        acc[i * 16 + q * 4 + 1] += a[i] * bv.y;
                        acc[i * 16 + q * 4 + 2] += a[i] * bv.z;
                        acc[i * 16 + q * 4 + 3] += a[i] * bv.w;
                    }
                }
            }
            __syncthreads();
        }
    }

    /* epilogue: out[tok] += gate * (acc + b2[e]) */
    #pragma unroll
    for (int i = 0; i < 4; i++) {
        int m = ty * 4 + i;
        if (r0 + m < cnt) {
            float g  = s_gate[m];
            int  tok = s_tok[m];
            #pragma unroll
            for (int q = 0; q < 4; q++) {
                #pragma unroll
                for (int j = 0; j < 4; j++) {
                    int n2 = q * 64 + tx * 4 + j;
                    atomicAdd(&out[tok * DMODEL + n2],
                              g * (acc[i * 16 + q * 4 + j] + b2[e * DMODEL + n2]));
                }
            }
        }
    }
}

/* ---------------- launch ---------------- */
extern "C" void kernel_launch(void* const* d_in, const int* in_sizes, int n_in,
                              void* d_out, int out_size) {
    const float* v0 = (const float*)d_in[0];
    const float* v1 = (const float*)d_in[1];
    const float* v2 = (const float*)d_in[2];
    const float* rw = (const float*)d_in[3];
    const float* ek = (const float*)d_in[4];
    const float* W1 = (const float*)d_in[5];
    const float* b1 = (const float*)d_in[6];
    const float* W2 = (const float*)d_in[7];
    const float* b2 = (const float*)d_in[8];
    float* out = (float*)d_out;

    cudaFuncSetAttribute(mlp_kernel, cudaFuncAttributeMaxDynamicSharedMemorySize,
                         SMEM_FLOATS * (int)sizeof(float));

    zero_kernel<<<(N_TOK * DMODEL + TPB - 1) / TPB, TPB>>>(out);
    prep_kernel<<<1, TPB>>>(rw, ek);
    gate_kernel<<<(NVIEW * N_TOK * 32) / TPB, TPB>>>(v0, v1, v2);

    dim3 grid(ASSIGN_TOTAL / BM, NEXP);   /* full worst-case coverage; empty tiles exit early */
    mlp_kernel<<<grid, TPB, SMEM_FLOATS * (int)sizeof(float)>>>(v0, v1, v2, W1, b1, W2, b2, out);
}

// round 4
// speedup vs baseline: 3.1215x; 3.1215x over previous
#include <cuda_runtime.h>
#include <cuda_bf16.h>
#include <mma.h>
#include <math.h>
#include <cstdint>

using namespace nvcuda;

#define N_TOK   8192
#define DMODEL  256
#define NEXP    16
#define NVIEW   3
#define TOPK    4
#define HDIM    1024
#define ASSIGN_TOTAL (NVIEW * N_TOK * TOPK)
#define CAP     ASSIGN_TOTAL
#define TPB     256
#define BM      128
#define NCHUNK  16
#define TPB5    512

#define TILE_ELEMS 16384   /* 256x64 per chunk */

/* dynamic SMEM layout (bytes) */
#define XHI_OFF 0                       /* [128][264] bf16 = 67584 */
#define XLO_OFF 67584
#define WB_OFF  135168                  /* 36864-byte W staging / fp32 scratch */
#define WLO_OFF (WB_OFF + 18432)
#define HHI_OFF 172032                  /* [128][72] bf16 = 18432 */
#define HLO_OFF 190464
#define SM_TOTAL 208896

/* ------------- static device scratch ------------- */
__device__ __nv_bfloat16 g_w1hi[NEXP * NCHUNK * TILE_ELEMS];
__device__ __nv_bfloat16 g_w1lo[NEXP * NCHUNK * TILE_ELEMS];
__device__ __nv_bfloat16 g_w2hi[NEXP * NCHUNK * TILE_ELEMS];
__device__ __nv_bfloat16 g_w2lo[NEXP * NCHUNK * TILE_ELEMS];
__device__ float g_comb[NVIEW * NEXP * DMODEL];
__device__ float g_kn2[NEXP];
__device__ int   g_cnt[NEXP];
__device__ int2  g_bucket[NEXP * CAP];

__device__ __forceinline__ uint32_t pack_hi_lo(float a0, float a1, uint32_t& lo) {
    __nv_bfloat16 h0 = __float2bfloat16_rn(a0), h1 = __float2bfloat16_rn(a1);
    float l0 = a0 - __bfloat162float(h0), l1 = a1 - __bfloat162float(h1);
    lo = ((uint32_t)__bfloat16_as_ushort(__float2bfloat16_rn(l1)) << 16)
       | (uint32_t)__bfloat16_as_ushort(__float2bfloat16_rn(l0));
    return ((uint32_t)__bfloat16_as_ushort(h1) << 16) | (uint32_t)__bfloat16_as_ushort(h0);
}
__device__ __forceinline__ float gelu_exact(float x) {
    return 0.5f * x * (1.0f + erff(x * 0.70710678118654752f));
}

/* ---------------- kernels 0-2: zero / router prep / gate (proven) ------------- */
__global__ void zero_kernel(float* __restrict__ out) {
    int i = blockIdx.x * blockDim.x + threadIdx.x;
    if (i < N_TOK * DMODEL) out[i] = 0.0f;
    if (i < NEXP) g_cnt[i] = 0;
}
__global__ void prep_kernel(const float* __restrict__ rw, const float* __restrict__ ek) {
    int t = threadIdx.x, lane = t & 31, w = t >> 5;
    for (int e = w; e < NEXP; e += 8) {
        float s = 0.f;
        #pragma unroll
        for (int j = 0; j < DMODEL; j += 32) { float x = ek[e * DMODEL + lane + j]; s += x * x; }
        #pragma unroll
        for (int o = 16; o; o >>= 1) s += __shfl_xor_sync(0xffffffffu, s, o);
        if (lane == 0) g_kn2[e] = s;
    }
    for (int i = t; i < NVIEW * NEXP * DMODEL; i += TPB) {
        int e = (i >> 8) & 15, d = i & 255;
        g_comb[i] = 2.0f * ek[e * DMODEL + d] + rw[i];
    }
}
__global__ void gate_kernel(const float* __restrict__ v0, const float* __restrict__ v1,
                            const float* __restrict__ v2) {
    int wg = (blockIdx.x * blockDim.x + threadIdx.x) >> 5;
    int lane = threadIdx.x & 31;
    if (wg >= NVIEW * N_TOK) return;
    int view = wg >> 13, tok = wg & (N_TOK - 1);
    const float* vp = (view == 0 ? v0 : (view == 1 ? v1 : v2)) + tok * DMODEL;
    float xr[8];
    #pragma unroll
    for (int j = 0; j < 8; j++) xr[j] = vp[lane + 32 * j];
    float lg[NEXP];
    const float* cb = g_comb + view * NEXP * DMODEL;
    #pragma unroll
    for (int e = 0; e < NEXP; e++) {
        float p = 0.f;
        #pragma unroll
        for (int j = 0; j < 8; j++) p += xr[j] * cb[e * DMODEL + lane + 32 * j];
        #pragma unroll
        for (int o = 16; o; o >>= 1) p += __shfl_xor_sync(0xffffffffu, p, o);
        lg[e] = p - g_kn2[e];
    }
    if (lane == 0) {
        float tv[TOPK]; int ti[TOPK]; unsigned used = 0;
        #pragma unroll
        for (int k = 0; k < TOPK; k++) {
            float best = -3.0e38f; int bi = 0;
            #pragma unroll
            for (int e = 0; e < NEXP; e++)
                if (!((used >> e) & 1u) && lg[e] > best) { best = lg[e]; bi = e; }
            used |= 1u << bi; tv[k] = best; ti[k] = bi;
        }
        float mx = tv[0], ex[TOPK], s = 0.f;
        #pragma unroll
        for (int k = 0; k < TOPK; k++) { ex[k] = expf(tv[k] - mx); s += ex[k]; }
        float inv = 1.0f / s;
        #pragma unroll
        for (int k = 0; k < TOPK; k++) {
            int e = ti[k];
            int slot = atomicAdd(&g_cnt[e], 1);
            g_bucket[e * CAP + slot] = make_int2(wg, __float_as_int(ex[k] * inv));
        }
    }
}

/* -------- kernel 3: split weights to bf16 hi/lo in MMA-ready [k][n] order ------ */
/* grid (E, 16, 2).  z=0: W1 chunk c -> [k=256][n=64]; z=1: W2 chunk c -> [k=64][n=256]. */
__global__ __launch_bounds__(TPB) void wprep_kernel(const float* __restrict__ W1,
                                                    const float* __restrict__ W2) {
    int e = blockIdx.x, c = blockIdx.y, z = blockIdx.z, t = threadIdx.x;
    size_t base = (size_t)(e * NCHUNK + c) * TILE_ELEMS;
    if (z == 0) {
        for (int idx = t; idx < TILE_ELEMS; idx += TPB) {
            int k = idx >> 6, n = idx & 63;
            float v = W1[(size_t)e * 262144 + (size_t)k * 1024 + c * 64 + n];
            __nv_bfloat16 hi = __float2bfloat16_rn(v);
            g_w1hi[base + idx] = hi;
            g_w1lo[base + idx] = __float2bfloat16_rn(v - __bfloat162float(hi));
        }
    } else {
        for (int idx = t; idx < TILE_ELEMS; idx += TPB) {
            int k = idx >> 8, n = idx & 255;
            float v = W2[(size_t)e * 262144 + (size_t)(c * 64 + k) * 256 + n];
            __nv_bfloat16 hi = __float2bfloat16_rn(v);
            g_w2hi[base + idx] = hi;
            g_w2lo[base + idx] = __float2bfloat16_rn(v - __bfloat162float(hi));
        }
    }
}

/* ---------------- kernel 4: WMMA grouped fused MLP ---------------- */
typedef wmma::fragment<wmma::matrix_a, 16, 16, 16, __nv_bfloat16, wmma::row_major> FragA;
typedef wmma::fragment<wmma::matrix_b, 16, 16, 16, __nv_bfloat16, wmma::row_major> FragB;
typedef wmma::fragment<wmma::accumulator, 16, 16, 16, float> FragC;

__global__ __launch_bounds__(TPB5, 1)
void mlp_mma(const float* __restrict__ v0, const float* __restrict__ v1,
             const float* __restrict__ v2,
             const float* __restrict__ b1, const float* __restrict__ b2,
             float* __restrict__ out) {
    int e = blockIdx.y;
    int cnt = g_cnt[e];
    int r0 = blockIdx.x * BM;
    if (r0 >= cnt) return;

    extern __shared__ char dyn[];
    __nv_bfloat16* Xhi = (__nv_bfloat16*)(dyn + XHI_OFF);
    __nv_bfloat16* Xlo = (__nv_bfloat16*)(dyn + XLO_OFF);
    __nv_bfloat16* Whi = (__nv_bfloat16*)(dyn + WB_OFF);
    __nv_bfloat16* Wlo = (__nv_bfloat16*)(dyn + WLO_OFF);
    float*         scr = (float*)(dyn + WB_OFF);
    __nv_bfloat16* Hhi = (__nv_bfloat16*)(dyn + HHI_OFF);
    __nv_bfloat16* Hlo = (__nv_bfloat16*)(dyn + HLO_OFF);

    __shared__ const float* s_ptr[BM];
    __shared__ float        s_gate[BM];
    __shared__ int          s_tok[BM];

    int t = threadIdx.x;
    if (t < BM) {
        int gr = r0 + t;
        if (gr < cnt) {
            int2 rec = g_bucket[e * CAP + gr];
            int view = rec.x >> 13, tok = rec.x & (N_TOK - 1);
            s_ptr[t] = (view == 0 ? v0 : (view == 1 ? v1 : v2)) + (size_t)tok * DMODEL;
            s_tok[t] = tok; s_gate[t] = __int_as_float(rec.y);
        } else { s_ptr[t] = v0; s_tok[t] = 0; s_gate[t] = 0.f; }
    }
    __syncthreads();

    /* stage X split: thread t -> row t>>2, 64-col quarter t&3 */
    {
        int m = t >> 2, q = t & 3;
        const float4* src = (const float4*)(s_ptr[m] + q * 64);
        uint32_t* dh = (uint32_t*)&Xhi[m * 264 + q * 64];
        uint32_t* dl = (uint32_t*)&Xlo[m * 264 + q * 64];
        #pragma unroll
        for (int j = 0; j < 16; j++) {
            float4 f = src[j];
            uint32_t l01, l23;
            uint32_t h01 = pack_hi_lo(f.x, f.y, l01);
            uint32_t h23 = pack_hi_lo(f.z, f.w, l23);
            dh[2 * j] = h01; dh[2 * j + 1] = h23;
            dl[2 * j] = l01; dl[2 * j + 1] = l23;
        }
    }

    int wid = t >> 5;
    int wm = wid >> 2, wn = wid & 3;     /* 4x4 warp grid */

    FragC c2[2][4];
    #pragma unroll
    for (int i = 0; i < 2; i++)
        #pragma unroll
        for (int n = 0; n < 4; n++) wmma::fill_fragment(c2[i][n], 0.0f);

    const __nv_bfloat16* w1h = g_w1hi + (size_t)e * NCHUNK * TILE_ELEMS;
    const __nv_bfloat16* w1l = g_w1lo + (size_t)e * NCHUNK * TILE_ELEMS;
    const __nv_bfloat16* w2h = g_w2hi + (size_t)e * NCHUNK * TILE_ELEMS;
    const __nv_bfloat16* w2l = g_w2lo + (size_t)e * NCHUNK * TILE_ELEMS;

    for (int c = 0; c < NCHUNK; c++) {
        /* ---------- GEMM1: C1[128][64] = X @ W1c, K=256 in 2 halves ---------- */
        FragC c1[2];
        wmma::fill_fragment(c1[0], 0.0f);
        wmma::fill_fragment(c1[1], 0.0f);
        #pragma unroll
        for (int h = 0; h < 2; h++) {
            __syncthreads();
            {   /* stage W1 half: [128 k][64 n] hi+lo, ld 72 */
                const uint4* sh = (const uint4*)(w1h + ((size_t)c * 256 + h * 128) * 64);
                const uint4* sl = (const uint4*)(w1l + ((size_t)c * 256 + h * 128) * 64);
                #pragma unroll
                for (int v = 0; v < 2; v++) {
                    int id = t + TPB5 * v;            /* 0..1023 = kl*8 + nb */
                    int kl = id >> 3, nb = id & 7;
                    *(uint4*)((char*)Whi + kl * 144 + nb * 16) = sh[id];
                    *(uint4*)((char*)Wlo + kl * 144 + nb * 16) = sl[id];
                }
            }
            __syncthreads();
            #pragma unroll
            for (int ks = 0; ks < 8; ks++) {
                int k0 = h * 128 + ks * 16;
                FragB bh, bl;
                wmma::load_matrix_sync(bh, Whi + ks * 16 * 72 + wn * 16, 72);
                wmma::load_matrix_sync(bl, Wlo + ks * 16 * 72 + wn * 16, 72);
                #pragma unroll
                for (int i = 0; i < 2; i++) {
                    FragA ah, al;
                    wmma::load_matrix_sync(ah, Xhi + (wm * 32 + i * 16) * 264 + k0, 264);
                    wmma::load_matrix_sync(al, Xlo + (wm * 32 + i * 16) * 264 + k0, 264);
                    wmma::mma_sync(c1[i], ah, bh, c1[i]);
                    wmma::mma_sync(c1[i], ah, bl, c1[i]);
                    wmma::mma_sync(c1[i], al, bh, c1[i]);
                }
            }
        }
        __syncthreads();
        /* C1 -> fp32 scratch (reuse W buffer), ld 68 */
        wmma::store_matrix_sync(&scr[(wm * 32) * 68 + wn * 16], c1[0], 68, wmma::mem_row_major);
        wmma::store_matrix_sync(&scr[(wm * 32 + 16) * 68 + wn * 16], c1[1], 68, wmma::mem_row_major);
        __syncthreads();
        /* bias + gelu + split -> H hi/lo */
        {
            int m = t >> 2, q = t & 3;
            const float* bb = b1 + e * HDIM + c * 64 + q * 16;
            uint32_t* dh = (uint32_t*)&Hhi[m * 72 + q * 16];
            uint32_t* dl = (uint32_t*)&Hlo[m * 72 + q * 16];
            #pragma unroll
            for (int j = 0; j < 8; j++) {
                float x0 = scr[m * 68 + q * 16 + 2 * j]     + __ldg(bb + 2 * j);
                float x1 = scr[m * 68 + q * 16 + 2 * j + 1] + __ldg(bb + 2 * j + 1);
                float g0 = gelu_exact(x0), g1 = gelu_exact(x1);
                uint32_t lo;
                dh[j] = pack_hi_lo(g0, g1, lo);
                dl[j] = lo;
            }
        }
        /* ---------- GEMM2: C2[128][256] += H @ W2c, K=64 in 2 halves ---------- */
        #pragma unroll
        for (int h = 0; h < 2; h++) {
            __syncthreads();
            {   /* stage W2 half: [32 k][256 n] hi+lo, ld 264 */
                const uint4* sh = (const uint4*)(w2h + ((size_t)c * 64 + h * 32) * 256);
                const uint4* sl = (const uint4*)(w2l + ((size_t)c * 64 + h * 32) * 256);
                #pragma unroll
                for (int v = 0; v < 2; v++) {
                    int id = t + TPB5 * v;            /* 0..1023 = kl*32 + nb */
                    int kl = id >> 5, nb = id & 31;
                    *(uint4*)((char*)Whi + kl * 528 + nb * 16) = sh[id];
                    *(uint4*)((char*)Wlo + kl * 528 + nb * 16) = sl[id];
                }
            }
            __syncthreads();
            #pragma unroll
            for (int ks = 0; ks < 2; ks++) {
                #pragma unroll
                for (int i = 0; i < 2; i++) {
                    FragA ah, al;
                    wmma::load_matrix_sync(ah, Hhi + (wm * 32 + i * 16) * 72 + h * 32 + ks * 16, 72);
                    wmma::load_matrix_sync(al, Hlo + (wm * 32 + i * 16) * 72 + h * 32 + ks * 16, 72);
                    #pragma unroll
                    for (int nf = 0; nf < 4; nf++) {
                        FragB bh, bl;
                        wmma::load_matrix_sync(bh, Whi + ks * 16 * 264 + wn * 64 + nf * 16, 264);
                        wmma::load_matrix_sync(bl, Wlo + ks * 16 * 264 + wn * 64 + nf * 16, 264);
                        wmma::mma_sync(c2[i][nf], ah, bh, c2[i][nf]);
                        wmma::mma_sync(c2[i][nf], ah, bl, c2[i][nf]);
                        wmma::mma_sync(c2[i][nf], al, bh, c2[i][nf]);
                    }
                }
            }
        }
    }

    /* ---------- epilogue: C2 -> out (gate, +b2), via fp32 scratch in quarters ---- */
    #pragma unroll
    for (int q = 0; q < 4; q++) {
        __syncthreads();
        if (wn == q) {
            #pragma unroll
            for (int i = 0; i < 2; i++)
                #pragma unroll
                for (int nf = 0; nf < 4; nf++)
                    wmma::store_matrix_sync(&scr[(wm * 32 + i * 16) * 68 + nf * 16],
                                            c2[i][nf], 68, wmma::mem_row_major);
        }
        __syncthreads();
        int m = t >> 2, cq = t & 3;
        float g = s_gate[m];
        if (g != 0.f) {
            int tok = s_tok[m];
            int nbase = q * 64 + cq * 16;
            #pragma unroll
            for (int j = 0; j < 16; j++) {
                int n = nbase + j;
                atomicAdd(&out[(size_t)tok * DMODEL + n],
                          g * (scr[m * 68 + cq * 16 + j] + __ldg(&b2[e * DMODEL + n])));
            }
        }
    }
}

/* ---------------- launch ---------------- */
extern "C" void kernel_launch(void* const* d_in, const int* in_sizes, int n_in,
                              void* d_out, int out_size) {
    const float* v0 = (const float*)d_in[0];
    const float* v1 = (const float*)d_in[1];
    const float* v2 = (const float*)d_in[2];
    const float* rw = (const float*)d_in[3];
    const float* ek = (const float*)d_in[4];
    const float* W1 = (const float*)d_in[5];
    const float* b1 = (const float*)d_in[6];
    const float* W2 = (const float*)d_in[7];
    const float* b2 = (const float*)d_in[8];
    float* out = (float*)d_out;

    cudaFuncSetAttribute(mlp_mma, cudaFuncAttributeMaxDynamicSharedMemorySize, SM_TOTAL);

    zero_kernel<<<(N_TOK * DMODEL + TPB - 1) / TPB, TPB>>>(out);
    prep_kernel<<<1, TPB>>>(rw, ek);
    wprep_kernel<<<dim3(NEXP, NCHUNK, 2), TPB>>>(W1, W2);
    gate_kernel<<<(NVIEW * N_TOK * 32) / TPB, TPB>>>(v0, v1, v2);

    dim3 grid(ASSIGN_TOTAL / BM, NEXP);
    mlp_mma<<<grid, TPB5, SM_TOTAL>>>(v0, v1, v2, b1, b2, out);
}